// round 17
// baseline (speedup 1.0000x reference)
#include <cuda_runtime.h>
#include <math.h>
#include <string.h>

// Problem constants (fixed by the dataset)
#define TT 1024
#define SS 512
#define DD 32
#define KK 64
#define LOG2PI 1.8378770664093453f

// Device-global state (no allocations allowed)
__device__ float        g_logden[SS];   // per-sequence sum log(denom)
__device__ unsigned int g_ticket = 0;   // block-completion ticket (self-resetting)

// ---- packed fp32x2 helpers (sm_103a) --------------------------------------
__device__ __forceinline__ unsigned long long ffma2(unsigned long long a,
                                                    unsigned long long b,
                                                    unsigned long long c) {
    unsigned long long d;
    asm("fma.rn.f32x2 %0, %1, %2, %3;" : "=l"(d) : "l"(a), "l"(b), "l"(c));
    return d;
}
__device__ __forceinline__ unsigned long long fadd2(unsigned long long a,
                                                    unsigned long long b) {
    unsigned long long d;
    asm("add.rn.f32x2 %0, %1, %2;" : "=l"(d) : "l"(a), "l"(b));
    return d;
}
__device__ __forceinline__ float2 unpack2(unsigned long long a) {
    float2 f;
    asm("mov.b64 {%0, %1}, %2;" : "=f"(f.x), "=f"(f.y) : "l"(a));
    return f;
}
__device__ __forceinline__ float rcp_approx(float x) {
    float y;
    asm("rcp.approx.f32 %0, %1;" : "=f"(y) : "f"(x));
    return y;
}
__device__ __forceinline__ unsigned long long packf2(float a, float b) {
    float2 f = make_float2(a, b);
    unsigned long long u; memcpy(&u, &f, 8);
    return u;
}

// ---------------------------------------------------------------------------
// Single fused kernel: one block (64 threads) per sequence, one thread per
// state k. Everything lives here:
//   - prologue: per-thread emission-parameter precompute (32 dims)
//   - forward recursion with DEPTH-4 x prefetch register ring (key fix: the
//     previous 1-step-deep prefetch put a ~577-cyc DRAM load on every step's
//     critical path; 4 steps of slack hides it completely)
//   - per step: ONE __syncthreads, no reduction tree (dsum piggybacked on the
//     transition dot over the same LDS.128 operands)
//   - epilogue: in-block logsum of the shared dsum ring -> g_logden[s]
//   - ticketed last block reduces g_logden -> -log_likelihood, resets ticket
// ---------------------------------------------------------------------------
__global__ __launch_bounds__(KK) void hmm_all_kernel(
    const float* __restrict__ data,      // [T, S, D]
    const float* __restrict__ initp,     // [K]
    const float* __restrict__ A,         // [K, K]
    const float* __restrict__ means,     // [K, D]
    const float* __restrict__ covars,    // [K, D]
    float* __restrict__ out,             // [S*K (+1)]
    int out_size)
{
    const int s    = blockIdx.x;
    const int k    = threadIdx.x;
    const int lane = k & 31;
    const int wrp  = k >> 5;

    __shared__ __align__(16) float  acc_sh[2][KK];  // unnormalized alpha
    __shared__ __align__(16) float2 xsh[2][DD];     // (x^2, x) ring
    __shared__ float dsr[TT];                       // per-step denominators
    __shared__ float red_sh[2];
    __shared__ unsigned int tick_sh;

    // ---- per-thread emission parameter precompute (fused) ----
    unsigned long long pp[DD];
    float base;
    {
        float m2 = 0.0f, lc = 0.0f;
        #pragma unroll
        for (int d = 0; d < DD; d++) {
            float c = covars[k * DD + d];
            float m = means [k * DD + d];
            float ic = 1.0f / c;
            pp[d] = packf2(-0.5f * ic, m * ic);
            m2 += m * m * ic;
            lc += logf(c);
        }
        base = -0.5f * (m2 + lc + (float)DD * LOG2PI);
    }
    const float initk = __ldg(&initp[k]);

    // Packed A column: Ac[j] = (A[2j][k], A[2j+1][k])
    unsigned long long Ac[KK / 2];
    #pragma unroll
    for (int j = 0; j < KK / 2; j++)
        Ac[j] = packf2(__ldg(&A[(2 * j) * KK + k]),
                       __ldg(&A[(2 * j + 1) * KK + k]));

    // ---- x staging: both warps, 16 dims each; DEPTH-4 register ring ----
    // xr[(t)&3] holds x_t, loaded 4 steps before it is staged into shared.
    const bool stager = (lane < 16);
    const int  d_my   = wrp * 16 + lane;            // valid when stager
    const float* dptr = data + (size_t)s * DD;      // data[(t*S+s)*D + d]
    float xr[4] = {0.f, 0.f, 0.f, 0.f};
    if (stager) {
        float x0 = __ldg(dptr + d_my);
        float x1 = __ldg(dptr + (size_t)1 * SS * DD + d_my);
        xsh[0][d_my] = make_float2(x0 * x0, x0);
        xsh[1][d_my] = make_float2(x1 * x1, x1);
        xr[2] = __ldg(dptr + (size_t)2 * SS * DD + d_my);
        xr[3] = __ldg(dptr + (size_t)3 * SS * DD + d_my);
        xr[0] = __ldg(dptr + (size_t)4 * SS * DD + d_my);
        xr[1] = __ldg(dptr + (size_t)5 * SS * DD + d_my);
    }
    __syncthreads();

    // Emission: logp = base + sum_d (x^2,x).(ninv,miv); 32 FFMA2
    auto emission = [&](int buf) -> float {
        const ulonglong2* xv = reinterpret_cast<const ulonglong2*>(xsh[buf]);
        unsigned long long a0 = 0ull, a1 = 0ull, a2 = 0ull, a3 = 0ull;
        #pragma unroll
        for (int i = 0; i < DD / 4; i += 2) {
            ulonglong2 v0 = xv[2 * i];
            ulonglong2 v1 = xv[2 * i + 1];
            ulonglong2 v2 = xv[2 * i + 2];
            ulonglong2 v3 = xv[2 * i + 3];
            a0 = ffma2(v0.x, pp[4 * i + 0], a0);
            a1 = ffma2(v0.y, pp[4 * i + 1], a1);
            a2 = ffma2(v1.x, pp[4 * i + 2], a2);
            a3 = ffma2(v1.y, pp[4 * i + 3], a3);
            a0 = ffma2(v2.x, pp[4 * i + 4], a0);
            a1 = ffma2(v2.y, pp[4 * i + 5], a1);
            a2 = ffma2(v3.x, pp[4 * i + 6], a2);
            a3 = ffma2(v3.y, pp[4 * i + 7], a3);
        }
        float2 f = unpack2(fadd2(fadd2(a0, a1), fadd2(a2, a3)));
        return __expf(base + f.x + f.y);
    };

    // ---- t = 0 ---- (dsum_0 computed by the piggyback sum in step 1)
    float acc = initk * emission(0);
    acc_sh[0][k] = acc;
    __syncthreads();

    // ---- t = 1 .. TT-1 ----
    #pragma unroll 2
    for (int t = 1; t < TT; t++) {
        const int cb = t & 1;
        const int pb = cb ^ 1;

        // Stage x_{t+1} from the ring (loaded 4 steps ago); refill with x_{t+5}
        if (stager) {
            const int ri = (t + 1) & 3;
            float xv = xr[ri];
            xsh[pb][d_my] = make_float2(xv * xv, xv);
            int t5 = (t + 5 < TT) ? (t + 5) : (TT - 1);
            xr[ri] = __ldg(dptr + (size_t)t5 * SS * DD + d_my);
        }

        // Transition dot (32 FFMA2) + piggyback dsum (32 fadd2) over the SAME
        // broadcast LDS.128 operands.
        const ulonglong2* a2p = reinterpret_cast<const ulonglong2*>(acc_sh[pb]);
        unsigned long long q0 = 0ull, q1 = 0ull, q2 = 0ull, q3 = 0ull;
        unsigned long long u0 = 0ull, u1 = 0ull, u2 = 0ull, u3 = 0ull;
        #pragma unroll
        for (int jj = 0; jj < 16; jj += 2) {
            ulonglong2 v0 = a2p[jj];
            ulonglong2 v1 = a2p[jj + 1];
            q0 = ffma2(v0.x, Ac[2 * jj + 0], q0);
            q1 = ffma2(v0.y, Ac[2 * jj + 1], q1);
            q2 = ffma2(v1.x, Ac[2 * jj + 2], q2);
            q3 = ffma2(v1.y, Ac[2 * jj + 3], q3);
            u0 = fadd2(u0, v0.x);
            u1 = fadd2(u1, v0.y);
            u2 = fadd2(u2, v1.x);
            u3 = fadd2(u3, v1.y);
        }
        float2 fq = unpack2(fadd2(fadd2(q0, q1), fadd2(q2, q3)));
        float2 fu = unpack2(fadd2(fadd2(u0, u1), fadd2(u2, u3)));
        float dsum = fu.x + fu.y;
        float r = rcp_approx(dsum);
        if (k == 0) dsr[t - 1] = dsum;          // shared ring, off hot path

        float dotn = (fq.x + fq.y) * r;         // rescale BEFORE p (underflow-safe)
        float p = emission(cb);
        acc = p * dotn;
        acc_sh[cb][k] = acc;

        __syncthreads();
    }

    // ---- epilogue: final dsum + alpha output ----
    {
        float v = acc;
        #pragma unroll
        for (int off = 16; off; off >>= 1)
            v += __shfl_xor_sync(0xffffffffu, v, off);
        if (lane == 0) red_sh[wrp] = v;
        __syncthreads();
        float dsum = red_sh[0] + red_sh[1];
        out[(size_t)s * KK + k] = acc * (1.0f / dsum);
        if (k == 0) dsr[TT - 1] = dsum;
    }
    __syncthreads();

    // ---- in-block logsum of this sequence's denominators ----
    {
        float lacc = 0.0f;
        #pragma unroll
        for (int i = 0; i < TT / KK; i++)
            lacc += __logf(dsr[i * KK + k]);
        #pragma unroll
        for (int off = 16; off; off >>= 1)
            lacc += __shfl_xor_sync(0xffffffffu, lacc, off);
        if (lane == 0) red_sh[wrp] = lacc;
        __syncthreads();
        if (k == 0) g_logden[s] = red_sh[0] + red_sh[1];
    }

    // ---- ticket: last block finishes the global reduction ----
    __threadfence();
    if (k == 0) tick_sh = atomicAdd(&g_ticket, 1u);
    __syncthreads();
    if (tick_sh == (unsigned)(gridDim.x - 1)) {
        __threadfence();
        float a = 0.0f;
        #pragma unroll
        for (int i = 0; i < SS / KK; i++)
            a += g_logden[i * KK + k];
        #pragma unroll
        for (int off = 16; off; off >>= 1)
            a += __shfl_xor_sync(0xffffffffu, a, off);
        if (lane == 0) red_sh[wrp] = a;
        __syncthreads();
        if (k == 0) {
            if (out_size > SS * KK)
                out[out_size - 1] = -(red_sh[0] + red_sh[1]);
            g_ticket = 0;                       // reset for next replay
        }
    }
}

extern "C" void kernel_launch(void* const* d_in, const int* in_sizes, int n_in,
                              void* d_out, int out_size) {
    const float* data  = (const float*)d_in[0];  // [T,S,D]
    const float* initp = (const float*)d_in[1];  // [K]
    const float* A     = (const float*)d_in[2];  // [K,K]
    const float* means = (const float*)d_in[3];  // [K,D]
    const float* covar = (const float*)d_in[4];  // [K,D]
    float* out = (float*)d_out;

    hmm_all_kernel<<<SS, KK>>>(data, initp, A, means, covar, out, out_size);
}